// round 16
// baseline (speedup 1.0000x reference)
#include <cuda_runtime.h>
#include <cuda_bf16.h>
#include <cstdint>

// ---------------------------------------------------------------------------
// GatedAttentionUnit: S=2048, B=4, E=1024, Z=128, H=2048
// R16: 256x128 CTA tile (512 thr, 16 warps 4Mx4N, per-warp 64x32) to raise
//      arithmetic intensity: 24 KB per K=16 chunk vs 768-cyc MMA floor =
//      32 B/cyc/SM, under the ~42 B/cyc L2 ceiling that capped R13-R15 at
//      ~51% tensor. cp.async 2-stage ring (61.4 KB < proven 73.7 KB),
//      ldmatrix.x4, pre-split bf16 hi/lo operands in global.
//      Math unchanged: mma.sync bf16 split-2 (hh+hl+lh), fp32 accum.
// ---------------------------------------------------------------------------

#define S_LEN 2048
#define BSZ 4
#define EDIM 1024
#define ZDIM 128
#define HDIM 2048
#define GEMM_THREADS 512
#define SCORE_THREADS 256

// rows: [hi 8w | lo 8w | pad 4w] = 20 words (80 B; 16B-aligned, ldmatrix
// banks 20r%32 = {0,20,8,28,16,4,24,12} conflict-free)
#define ROW_W 20
#define A_ROWS 256
#define B_ROWS 128
#define A_W (A_ROWS * ROW_W)             // 5120 words
#define B_W (B_ROWS * ROW_W)             // 2560 words
#define STAGE_W (A_W + B_W)              // 7680 words = 30720 B
#define SMEM_DYN_BYTES (2 * STAGE_W * 4) // 61440 B (< proven 73728)

// ---------------- scratch (device globals; allocation-free) ----------------
__device__ float d_u [(size_t)S_LEN * BSZ * HDIM];
__device__ float d_q [(size_t)BSZ * S_LEN * ZDIM];
__device__ float d_kk[(size_t)BSZ * S_LEN * ZDIM];

__device__ __nv_bfloat16 d_xh [(size_t)S_LEN * BSZ * EDIM];
__device__ __nv_bfloat16 d_xl [(size_t)S_LEN * BSZ * EDIM];
__device__ __nv_bfloat16 d_pwh[(size_t)(2 * HDIM + ZDIM) * EDIM];
__device__ __nv_bfloat16 d_pwl[(size_t)(2 * HDIM + ZDIM) * EDIM];
__device__ __nv_bfloat16 d_owh[(size_t)EDIM * HDIM];
__device__ __nv_bfloat16 d_owl[(size_t)EDIM * HDIM];
__device__ __nv_bfloat16 d_vTh[(size_t)BSZ * HDIM * S_LEN];
__device__ __nv_bfloat16 d_vTl[(size_t)BSZ * HDIM * S_LEN];
__device__ __nv_bfloat16 d_ah [(size_t)BSZ * S_LEN * S_LEN];
__device__ __nv_bfloat16 d_al [(size_t)BSZ * S_LEN * S_LEN];
__device__ __nv_bfloat16 d_gh [(size_t)S_LEN * BSZ * HDIM];
__device__ __nv_bfloat16 d_gl [(size_t)S_LEN * BSZ * HDIM];

// ---------------------------------------------------------------------------
__device__ __forceinline__ void mma16816(float* d, const uint32_t* a, const uint32_t* b) {
    asm volatile(
        "mma.sync.aligned.m16n8k16.row.col.f32.bf16.bf16.f32 "
        "{%0,%1,%2,%3}, {%4,%5,%6,%7}, {%8,%9}, {%0,%1,%2,%3};"
        : "+f"(d[0]), "+f"(d[1]), "+f"(d[2]), "+f"(d[3])
        : "r"(a[0]), "r"(a[1]), "r"(a[2]), "r"(a[3]), "r"(b[0]), "r"(b[1]));
}

__device__ __forceinline__ void ldm_x4(uint32_t& r0, uint32_t& r1,
                                       uint32_t& r2, uint32_t& r3, uint32_t addr) {
    asm volatile("ldmatrix.sync.aligned.m8n8.x4.shared.b16 {%0,%1,%2,%3}, [%4];"
                 : "=r"(r0), "=r"(r1), "=r"(r2), "=r"(r3) : "r"(addr));
}

__device__ __forceinline__ void split2(float v, __nv_bfloat16& h, __nv_bfloat16& l) {
    h = __float2bfloat16_rn(v);
    l = __float2bfloat16_rn(v - __bfloat162float(h));
}

// ---------------------------------------------------------------------------
// cp.async staging: one K=16 chunk = 1536 16B segs (A: 1024, B: 512);
// 512 threads x 3 segs each. Row layout: [hi(2 segs) | lo(2 segs)].
// ---------------------------------------------------------------------------
__device__ __forceinline__ void stage_chunk(
    const __nv_bfloat16* __restrict__ Ahi, const __nv_bfloat16* __restrict__ Alo, int lda,
    const __nv_bfloat16* __restrict__ Bhi, const __nv_bfloat16* __restrict__ Blo, int ldb,
    int c, uint32_t sbase)
{
    const int tid = threadIdx.x;
#pragma unroll
    for (int u = 0; u < 3; ++u) {
        int seg = u * GEMM_THREADS + tid;
        bool isA = seg < 1024;
        int s = isA ? seg : seg - 1024;
        int row = s >> 2, part = s & 3;      // part: 0-1 hi, 2-3 lo
        const __nv_bfloat16* gb = isA ? ((part < 2) ? Ahi : Alo)
                                      : ((part < 2) ? Bhi : Blo);
        int ld = isA ? lda : ldb;
        const void* g = gb + (size_t)row * ld + c * 16 + (part & 1) * 8;
        uint32_t sa = sbase + ((uint32_t)((isA ? 0 : A_W) + row * ROW_W + part * 4) << 2);
        asm volatile("cp.async.cg.shared.global [%0], [%1], 16;" :: "r"(sa), "l"(g));
    }
}

// ---------------------------------------------------------------------------
// Core GEMM: acc(256x128) = A(256xK) * B(128xK)^T from pre-split bf16 hi/lo.
// 16 warps as 4(M) x 4(N); per-warp 64x32 via 4x4 m16n8k16 tiles.
// Fragment loads via ldmatrix.x4. Split-2: A-hi(bh,bl) then A-lo(bh).
// 2-stage cp.async pipeline, one barrier per chunk; nChunks = K/16 chunks.
// ---------------------------------------------------------------------------
extern __shared__ uint32_t smw[];

__device__ __forceinline__ void mma_gemm(
    const __nv_bfloat16* __restrict__ Ahi, const __nv_bfloat16* __restrict__ Alo, int lda,
    const __nv_bfloat16* __restrict__ Bhi, const __nv_bfloat16* __restrict__ Blo, int ldb,
    int nChunks, float acc[4][4][4])
{
    const int tid = threadIdx.x;
    const int lane = tid & 31, wid = tid >> 5;
    const int wm = wid & 3, wn = wid >> 2;
    uint32_t sb = (uint32_t)__cvta_generic_to_shared(smw);

    // per-thread ldmatrix address offsets (words), relative to stage base
    const int t8 = lane & 7, m4 = lane >> 3;   // m4 = matrix id 0..3
    const int aoffw = (wm * 64 + t8 + (m4 & 1) * 8) * ROW_W + (m4 >> 1) * 4;
    const int boffw = (wn * 32 + t8 + (m4 >> 1) * 8) * ROW_W + (m4 & 1) * 4;

    stage_chunk(Ahi, Alo, lda, Bhi, Blo, ldb, 0, sb);
    asm volatile("cp.async.commit_group;" ::: "memory");

    for (int c = 0; c < nChunks; ++c) {
        asm volatile("cp.async.wait_group 0;" ::: "memory");  // stage c landed
        __syncthreads();   // all warps: stage c visible AND iter c-1 reads done

        if (c + 1 < nChunks) {
            stage_chunk(Ahi, Alo, lda, Bhi, Blo, ldb, c + 1,
                        sb + (uint32_t)(((c + 1) & 1) * (STAGE_W * 4)));
            asm volatile("cp.async.commit_group;" ::: "memory");
        }

        const uint32_t stg = sb + (uint32_t)((c & 1) * (STAGE_W * 4));
        const uint32_t aB = stg + (uint32_t)(aoffw << 2);
        const uint32_t bB = stg + (uint32_t)((A_W + boffw) << 2);

        uint32_t av[4][4], bh[4][2], bl[4][2];
#pragma unroll
        for (int mi = 0; mi < 4; ++mi)     // A-hi (16 rows x k0-15 each)
            ldm_x4(av[mi][0], av[mi][1], av[mi][2], av[mi][3],
                   aB + ((mi * 16 * ROW_W) << 2));
#pragma unroll
        for (int np = 0; np < 2; ++np) {   // B-hi / B-lo (2 ni per ldmatrix)
            ldm_x4(bh[2 * np][0], bh[2 * np][1], bh[2 * np + 1][0], bh[2 * np + 1][1],
                   bB + ((np * 16 * ROW_W) << 2));
            ldm_x4(bl[2 * np][0], bl[2 * np][1], bl[2 * np + 1][0], bl[2 * np + 1][1],
                   bB + ((np * 16 * ROW_W + 8) << 2));
        }
#pragma unroll
        for (int mi = 0; mi < 4; ++mi)
#pragma unroll
            for (int ni = 0; ni < 4; ++ni)
                mma16816(acc[mi][ni], av[mi], bh[ni]);
#pragma unroll
        for (int mi = 0; mi < 4; ++mi)
#pragma unroll
            for (int ni = 0; ni < 4; ++ni)
                mma16816(acc[mi][ni], av[mi], bl[ni]);
#pragma unroll
        for (int mi = 0; mi < 4; ++mi)     // A-lo (reuse av regs)
            ldm_x4(av[mi][0], av[mi][1], av[mi][2], av[mi][3],
                   aB + ((mi * 16 * ROW_W + 8) << 2));
#pragma unroll
        for (int mi = 0; mi < 4; ++mi)
#pragma unroll
            for (int ni = 0; ni < 4; ++ni)
                mma16816(acc[mi][ni], av[mi], bh[ni]);
    }
}

__device__ __forceinline__ float silu(float v) { return v / (1.0f + __expf(-v)); }

// Per-thread element coordinates inside the 256x128 tile:
//   r = wm*64 + mi*16 + g + (e>=2 ? 8 : 0)
//   c = wn*32 + ni*8 + tg*2 + (e&1)

// ---------------------------------------------------------------------------
// K0: elementwise fp32 -> bf16 hi/lo split (for x, proj_w, out_w)
// ---------------------------------------------------------------------------
__global__ void k_split(const float* __restrict__ src,
                        __nv_bfloat16* __restrict__ hi,
                        __nv_bfloat16* __restrict__ lo, int n)
{
    int i = (blockIdx.x * blockDim.x + threadIdx.x) * 4;
    if (i < n) {
        float4 f = *(const float4*)(src + i);
        __nv_bfloat16 h[4], l[4];
        split2(f.x, h[0], l[0]); split2(f.y, h[1], l[1]);
        split2(f.z, h[2], l[2]); split2(f.w, h[3], l[3]);
        *(uint2*)(hi + i) = *(const uint2*)h;
        *(uint2*)(lo + i) = *(const uint2*)l;
    }
}

// ---------------------------------------------------------------------------
// K1: proj = silu(x @ Wp^T + bp); split into u / vT(hi,lo) / q,k
// ---------------------------------------------------------------------------
__global__ void __launch_bounds__(GEMM_THREADS, 1)
k_proj_t(const float* __restrict__ pb, const float* __restrict__ gamma,
         const float* __restrict__ beta)
{
    const int bx = blockIdx.x, by = blockIdx.y;
    float acc[4][4][4] = {};
    mma_gemm(d_xh + (size_t)by * 256 * EDIM, d_xl + (size_t)by * 256 * EDIM, EDIM,
             d_pwh + (size_t)bx * 128 * EDIM, d_pwl + (size_t)bx * 128 * EDIM, EDIM,
             EDIM / 16, acc);

    const int lane = threadIdx.x & 31, wid = threadIdx.x >> 5;
    const int g = lane >> 2, tg = lane & 3;
    const int wm = wid & 3, wn = wid >> 2;
#pragma unroll
    for (int mi = 0; mi < 4; ++mi) {
#pragma unroll
        for (int ni = 0; ni < 4; ++ni) {
#pragma unroll
            for (int e = 0; e < 4; ++e) {
                int r = by * 256 + wm * 64 + mi * 16 + g + ((e >> 1) ? 8 : 0);
                int cg = bx * 128 + wn * 32 + ni * 8 + tg * 2 + (e & 1);
                float v = silu(acc[mi][ni][e] + pb[cg]);
                int s = r >> 2, b = r & 3;
                if (bx < 16) {
                    d_u[(size_t)r * HDIM + cg] = v;
                } else if (bx < 32) {
                    int h = cg - HDIM;
                    size_t vi = ((size_t)b * HDIM + h) * S_LEN + s;
                    __nv_bfloat16 vh, vl;
                    split2(v, vh, vl);
                    d_vTh[vi] = vh;
                    d_vTl[vi] = vl;
                } else {
                    int zi = cg - 2 * HDIM;
                    size_t qi = ((size_t)b * S_LEN + s) * ZDIM + zi;
                    d_q[qi]  = v * gamma[zi]        + beta[zi];
                    d_kk[qi] = v * gamma[ZDIM + zi] + beta[ZDIM + zi];
                }
            }
        }
    }
}

// ---------------------------------------------------------------------------
// K2: scores = relu(q k^T / S + bias)^2, causal -> attn hi/lo (fp32 FFMA)
// ---------------------------------------------------------------------------
#define BK 16
__global__ void __launch_bounds__(SCORE_THREADS, 2)
k_score(const float* __restrict__ rpb)
{
    const int by = blockIdx.y, bx = blockIdx.x, b = blockIdx.z;
    if (bx > by) return;
    __shared__ float As[BK][129];
    __shared__ float Bs[BK][129];
    float acc[8][8] = {};
    const float* Ag0 = d_q  + ((size_t)b * S_LEN + by * 128) * ZDIM;
    const float* Bg0 = d_kk + ((size_t)b * S_LEN + bx * 128) * ZDIM;
    const int tid = threadIdx.x;
    const int lr = tid >> 2, lc = (tid & 3) << 2;
    const float* Ag = Ag0 + lr * ZDIM + lc;
    const float* Bg = Bg0 + lr * ZDIM + lc;
    const int ty = tid >> 4, tx = tid & 15;
    for (int kk = 0; kk < ZDIM / BK; ++kk) {
        float4 a0 = *(const float4*)(Ag);
        float4 a1 = *(const float4*)(Ag + 64 * ZDIM);
        float4 b0 = *(const float4*)(Bg);
        float4 b1 = *(const float4*)(Bg + 64 * ZDIM);
        __syncthreads();
        As[lc + 0][lr] = a0.x; As[lc + 1][lr] = a0.y; As[lc + 2][lr] = a0.z; As[lc + 3][lr] = a0.w;
        As[lc + 0][lr + 64] = a1.x; As[lc + 1][lr + 64] = a1.y; As[lc + 2][lr + 64] = a1.z; As[lc + 3][lr + 64] = a1.w;
        Bs[lc + 0][lr] = b0.x; Bs[lc + 1][lr] = b0.y; Bs[lc + 2][lr] = b0.z; Bs[lc + 3][lr] = b0.w;
        Bs[lc + 0][lr + 64] = b1.x; Bs[lc + 1][lr + 64] = b1.y; Bs[lc + 2][lr + 64] = b1.z; Bs[lc + 3][lr + 64] = b1.w;
        __syncthreads();
#pragma unroll
        for (int k = 0; k < BK; ++k) {
            float ar[8], br[8];
#pragma unroll
            for (int i = 0; i < 8; ++i) ar[i] = As[k][i * 16 + ty];
#pragma unroll
            for (int j = 0; j < 8; ++j) br[j] = Bs[k][j * 16 + tx];
#pragma unroll
            for (int i = 0; i < 8; ++i)
#pragma unroll
                for (int j = 0; j < 8; ++j) acc[i][j] += ar[i] * br[j];
        }
        Ag += BK; Bg += BK;
    }
#pragma unroll
    for (int i = 0; i < 8; ++i) {
#pragma unroll
        for (int j = 0; j < 8; ++j) {
            int r = by * 128 + i * 16 + ty;
            int c = bx * 128 + j * 16 + tx;
            float v = acc[i][j] * (1.0f / (float)S_LEN) + rpb[(S_LEN - 1) + c - r];
            float a = (c > r) ? 0.0f : fmaxf(v, 0.0f);
            float a2 = a * a;
            size_t idx = ((size_t)b * S_LEN + r) * S_LEN + c;
            __nv_bfloat16 h, l;
            split2(a2, h, l);
            d_ah[idx] = h;
            d_al[idx] = l;
        }
    }
}

// ---------------------------------------------------------------------------
// K3: g = (attn @ v) * u  (K truncated at diagonal block) -> g hi/lo
// ---------------------------------------------------------------------------
__global__ void __launch_bounds__(GEMM_THREADS, 1)
k_av_t()
{
    const int bx = blockIdx.x, by = blockIdx.y, b = blockIdx.z;
    float acc[4][4][4] = {};
    mma_gemm(d_ah + ((size_t)b * S_LEN + by * 256) * S_LEN,
             d_al + ((size_t)b * S_LEN + by * 256) * S_LEN, S_LEN,
             d_vTh + ((size_t)b * HDIM + bx * 128) * S_LEN,
             d_vTl + ((size_t)b * HDIM + bx * 128) * S_LEN, S_LEN,
             (by + 1) * 16, acc);

    const int lane = threadIdx.x & 31, wid = threadIdx.x >> 5;
    const int g = lane >> 2, tg = lane & 3;
    const int wm = wid & 3, wn = wid >> 2;
#pragma unroll
    for (int mi = 0; mi < 4; ++mi) {
#pragma unroll
        for (int ni = 0; ni < 4; ++ni) {
#pragma unroll
            for (int e = 0; e < 4; ++e) {
                int q = by * 256 + wm * 64 + mi * 16 + g + ((e >> 1) ? 8 : 0);
                int h = bx * 128 + wn * 32 + ni * 8 + tg * 2 + (e & 1);
                size_t idx = ((size_t)q * BSZ + b) * HDIM + h;
                float gv = acc[mi][ni][e] * d_u[idx];
                __nv_bfloat16 gh, gl;
                split2(gv, gh, gl);
                d_gh[idx] = gh;
                d_gl[idx] = gl;
            }
        }
    }
}

// ---------------------------------------------------------------------------
// K4: out = g @ Wo^T + bo
// ---------------------------------------------------------------------------
__global__ void __launch_bounds__(GEMM_THREADS, 1)
k_out_t(const float* __restrict__ ob, float* __restrict__ out)
{
    const int bx = blockIdx.x, by = blockIdx.y;
    float acc[4][4][4] = {};
    mma_gemm(d_gh + (size_t)by * 256 * HDIM, d_gl + (size_t)by * 256 * HDIM, HDIM,
             d_owh + (size_t)bx * 128 * HDIM, d_owl + (size_t)bx * 128 * HDIM, HDIM,
             HDIM / 16, acc);

    const int lane = threadIdx.x & 31, wid = threadIdx.x >> 5;
    const int g = lane >> 2, tg = lane & 3;
    const int wm = wid & 3, wn = wid >> 2;
#pragma unroll
    for (int mi = 0; mi < 4; ++mi) {
#pragma unroll
        for (int ni = 0; ni < 4; ++ni) {
#pragma unroll
            for (int e = 0; e < 4; ++e) {
                int r = by * 256 + wm * 64 + mi * 16 + g + ((e >> 1) ? 8 : 0);
                int c = bx * 128 + wn * 32 + ni * 8 + tg * 2 + (e & 1);
                out[(size_t)r * EDIM + c] = acc[mi][ni][e] + ob[c];
            }
        }
    }
}

// ---------------------------------------------------------------------------
extern "C" void kernel_launch(void* const* d_in, const int* in_sizes, int n_in,
                              void* d_out, int out_size)
{
    const float* x      = (const float*)d_in[0];
    const float* proj_w = (const float*)d_in[2];
    const float* proj_b = (const float*)d_in[3];
    const float* out_w  = (const float*)d_in[4];
    const float* out_b  = (const float*)d_in[5];
    const float* gamma  = (const float*)d_in[6];
    const float* beta   = (const float*)d_in[7];
    const float* rpb    = (const float*)d_in[8];
    float* out = (float*)d_out;

    cudaFuncSetAttribute(k_proj_t, cudaFuncAttributeMaxDynamicSharedMemorySize, SMEM_DYN_BYTES);
    cudaFuncSetAttribute(k_av_t,   cudaFuncAttributeMaxDynamicSharedMemorySize, SMEM_DYN_BYTES);
    cudaFuncSetAttribute(k_out_t,  cudaFuncAttributeMaxDynamicSharedMemorySize, SMEM_DYN_BYTES);

    __nv_bfloat16 *xh, *xl, *pwh, *pwl, *owh, *owl;
    cudaGetSymbolAddress((void**)&xh,  d_xh);
    cudaGetSymbolAddress((void**)&xl,  d_xl);
    cudaGetSymbolAddress((void**)&pwh, d_pwh);
    cudaGetSymbolAddress((void**)&pwl, d_pwl);
    cudaGetSymbolAddress((void**)&owh, d_owh);
    cudaGetSymbolAddress((void**)&owl, d_owl);

    const int nx = S_LEN * BSZ * EDIM;
    const int npw = (2 * HDIM + ZDIM) * EDIM;
    const int now = EDIM * HDIM;
    k_split<<<nx  / 1024, 256>>>(x,      xh,  xl,  nx);
    k_split<<<npw / 1024, 256>>>(proj_w, pwh, pwl, npw);
    k_split<<<now / 1024, 256>>>(out_w,  owh, owl, now);

    // M tiles of 256 rows: 8192/256 = 32
    k_proj_t<<<dim3(33, 32), dim3(GEMM_THREADS), SMEM_DYN_BYTES>>>(proj_b, gamma, beta);
    k_score <<<dim3(16, 16, 4), dim3(SCORE_THREADS)>>>(rpb);
    k_av_t  <<<dim3(16, 8, 4), dim3(GEMM_THREADS), SMEM_DYN_BYTES>>>();
    k_out_t <<<dim3(8, 32), dim3(GEMM_THREADS), SMEM_DYN_BYTES>>>(out_b, out);
}

// round 17
// speedup vs baseline: 1.3476x; 1.3476x over previous
#include <cuda_runtime.h>
#include <cuda_bf16.h>
#include <cstdint>

// ---------------------------------------------------------------------------
// GatedAttentionUnit: S=2048, B=4, E=1024, Z=128, H=2048
// R17: revert to R15 (best: 128x128 tile, 2 CTAs/SM, K=32 cp.async ring,
//      ldmatrix.x4, one barrier/chunk) + chunk-head reorder: fragment loads
//      and first MMA pass issue BEFORE the next chunk's cp.async burst, so
//      tensor work starts immediately after the barrier and LSU staging
//      drains under HMMA. R16 (bigger tile, 1 CTA) regressed and is dropped.
//      Math unchanged: mma.sync bf16 split-2 (hh+hl+lh), fp32 accum.
// ---------------------------------------------------------------------------

#define S_LEN 2048
#define BSZ 4
#define EDIM 1024
#define ZDIM 128
#define HDIM 2048
#define GEMM_THREADS 256
#define SCORE_THREADS 256

// smem stage: A tile + B tile; tile = 128 rows x [hi 16w | lo 16w | pad 4]
// ROW_W = 36 words (144 B: 16B-aligned rows; banks 4r -> ldmatrix conflict-free)
#define ROW_W 36
#define TILE_W (128 * ROW_W)             // 4608 words
#define STAGE_W (2 * TILE_W)             // 9216 words = 36864 B
#define SMEM_DYN_BYTES (2 * STAGE_W * 4) // 73728 B per CTA (container-proven)

// ---------------- scratch (device globals; allocation-free) ----------------
__device__ float d_u [(size_t)S_LEN * BSZ * HDIM];
__device__ float d_q [(size_t)BSZ * S_LEN * ZDIM];
__device__ float d_kk[(size_t)BSZ * S_LEN * ZDIM];

__device__ __nv_bfloat16 d_xh [(size_t)S_LEN * BSZ * EDIM];
__device__ __nv_bfloat16 d_xl [(size_t)S_LEN * BSZ * EDIM];
__device__ __nv_bfloat16 d_pwh[(size_t)(2 * HDIM + ZDIM) * EDIM];
__device__ __nv_bfloat16 d_pwl[(size_t)(2 * HDIM + ZDIM) * EDIM];
__device__ __nv_bfloat16 d_owh[(size_t)EDIM * HDIM];
__device__ __nv_bfloat16 d_owl[(size_t)EDIM * HDIM];
__device__ __nv_bfloat16 d_vTh[(size_t)BSZ * HDIM * S_LEN];
__device__ __nv_bfloat16 d_vTl[(size_t)BSZ * HDIM * S_LEN];
__device__ __nv_bfloat16 d_ah [(size_t)BSZ * S_LEN * S_LEN];
__device__ __nv_bfloat16 d_al [(size_t)BSZ * S_LEN * S_LEN];
__device__ __nv_bfloat16 d_gh [(size_t)S_LEN * BSZ * HDIM];
__device__ __nv_bfloat16 d_gl [(size_t)S_LEN * BSZ * HDIM];

// ---------------------------------------------------------------------------
__device__ __forceinline__ void mma16816(float* d, const uint32_t* a, const uint32_t* b) {
    asm volatile(
        "mma.sync.aligned.m16n8k16.row.col.f32.bf16.bf16.f32 "
        "{%0,%1,%2,%3}, {%4,%5,%6,%7}, {%8,%9}, {%0,%1,%2,%3};"
        : "+f"(d[0]), "+f"(d[1]), "+f"(d[2]), "+f"(d[3])
        : "r"(a[0]), "r"(a[1]), "r"(a[2]), "r"(a[3]), "r"(b[0]), "r"(b[1]));
}

__device__ __forceinline__ void ldm_x4(uint32_t& r0, uint32_t& r1,
                                       uint32_t& r2, uint32_t& r3, uint32_t addr) {
    asm volatile("ldmatrix.sync.aligned.m8n8.x4.shared.b16 {%0,%1,%2,%3}, [%4];"
                 : "=r"(r0), "=r"(r1), "=r"(r2), "=r"(r3) : "r"(addr));
}

__device__ __forceinline__ void split2(float v, __nv_bfloat16& h, __nv_bfloat16& l) {
    h = __float2bfloat16_rn(v);
    l = __float2bfloat16_rn(v - __bfloat162float(h));
}

// ---------------------------------------------------------------------------
// cp.async staging: one K=32 chunk of A and B tiles (hi+lo) = 2048 16B segs;
// 256 threads x 8 segs each.
// ---------------------------------------------------------------------------
__device__ __forceinline__ void stage_chunk(
    const __nv_bfloat16* __restrict__ Ahi, const __nv_bfloat16* __restrict__ Alo, int lda,
    const __nv_bfloat16* __restrict__ Bhi, const __nv_bfloat16* __restrict__ Blo, int ldb,
    int c, uint32_t sbase)
{
    const int tid = threadIdx.x;
#pragma unroll
    for (int u = 0; u < 8; ++u) {
        int seg  = u * GEMM_THREADS + tid;
        int tile = seg >> 10;          // 0 = A, 1 = B
        int s10  = seg & 1023;
        int row  = s10 >> 3;
        int part = s10 & 7;            // 0-3 hi, 4-7 lo
        int p4   = part & 3;
        const __nv_bfloat16* gb;
        int ld;
        if (tile == 0) { gb = (part < 4) ? Ahi : Alo; ld = lda; }
        else           { gb = (part < 4) ? Bhi : Blo; ld = ldb; }
        const void* g = gb + (size_t)row * ld + c * 32 + p4 * 8;
        uint32_t sa = sbase + ((uint32_t)(tile * TILE_W + row * ROW_W
                     + ((part < 4) ? p4 * 4 : 16 + p4 * 4)) << 2);
        asm volatile("cp.async.cg.shared.global [%0], [%1], 16;" :: "r"(sa), "l"(g));
    }
}

// ---------------------------------------------------------------------------
// Core GEMM: acc(128x128) = A(128xK) * B(128xK)^T from pre-split bf16 hi/lo.
// 8 warps as 2(M) x 4(N); per-warp 64x32 via 4x4 m16n8k16 tiles.
// Fragment loads via ldmatrix.x4. Split-2: A-hi(bh,bl) then A-lo(bh).
// 2-stage cp.async pipeline, one barrier/chunk; staging issued after the
// first MMA pass so HMMA starts immediately post-barrier.
// ---------------------------------------------------------------------------
extern __shared__ uint32_t smw[];

__device__ __forceinline__ void mma_gemm(
    const __nv_bfloat16* __restrict__ Ahi, const __nv_bfloat16* __restrict__ Alo, int lda,
    const __nv_bfloat16* __restrict__ Bhi, const __nv_bfloat16* __restrict__ Blo, int ldb,
    int nChunks, float acc[4][4][4])
{
    const int tid = threadIdx.x;
    const int lane = tid & 31, wid = tid >> 5;
    const int wm = wid & 1, wn = wid >> 1;
    uint32_t sb = (uint32_t)__cvta_generic_to_shared(smw);

    // per-thread ldmatrix address offsets (words), relative to tile base
    const int t8 = lane & 7, m4 = lane >> 3;         // m4 = matrix id 0..3
    const int aoffw = (wm * 64 + t8 + (m4 & 1) * 8) * ROW_W + (m4 >> 1) * 4;
    const int boffw = (wn * 32 + t8 + (m4 >> 1) * 8) * ROW_W + (m4 & 1) * 4;

    stage_chunk(Ahi, Alo, lda, Bhi, Blo, ldb, 0, sb);
    asm volatile("cp.async.commit_group;" ::: "memory");

    for (int c = 0; c < nChunks; ++c) {
        asm volatile("cp.async.wait_group 0;" ::: "memory");  // stage c landed
        __syncthreads();   // all warps: stage c visible AND iter c-1 reads done

        const uint32_t stg = sb + (uint32_t)((c & 1) * (STAGE_W * 4));
        const uint32_t aB = stg + (uint32_t)(aoffw << 2);
        const uint32_t bB = stg + (uint32_t)((TILE_W + boffw) << 2);

        uint32_t av[4][4], bh[4][2], bl[4][2];

        // ---- ks = 0: fragments first, MMAs ASAP --------------------------
#pragma unroll
        for (int mi = 0; mi < 4; ++mi)     // A-hi
            ldm_x4(av[mi][0], av[mi][1], av[mi][2], av[mi][3],
                   aB + ((mi * 576) << 2));
#pragma unroll
        for (int np = 0; np < 2; ++np) {   // B-hi / B-lo
            ldm_x4(bh[2 * np][0], bh[2 * np][1], bh[2 * np + 1][0], bh[2 * np + 1][1],
                   bB + ((np * 576) << 2));
            ldm_x4(bl[2 * np][0], bl[2 * np][1], bl[2 * np + 1][0], bl[2 * np + 1][1],
                   bB + ((np * 576 + 16) << 2));
        }
#pragma unroll
        for (int mi = 0; mi < 4; ++mi)     // hh
#pragma unroll
            for (int ni = 0; ni < 4; ++ni)
                mma16816(acc[mi][ni], av[mi], bh[ni]);

        // stage c+1 now: LSU burst drains under the hh HMMAs
        if (c + 1 < nChunks) {
            stage_chunk(Ahi, Alo, lda, Bhi, Blo, ldb, c + 1,
                        sb + (uint32_t)(((c + 1) & 1) * (STAGE_W * 4)));
            asm volatile("cp.async.commit_group;" ::: "memory");
        }

#pragma unroll
        for (int mi = 0; mi < 4; ++mi)     // hl
#pragma unroll
            for (int ni = 0; ni < 4; ++ni)
                mma16816(acc[mi][ni], av[mi], bl[ni]);
#pragma unroll
        for (int mi = 0; mi < 4; ++mi)     // A-lo (reuse av)
            ldm_x4(av[mi][0], av[mi][1], av[mi][2], av[mi][3],
                   aB + ((mi * 576 + 16) << 2));
#pragma unroll
        for (int mi = 0; mi < 4; ++mi)     // lh
#pragma unroll
            for (int ni = 0; ni < 4; ++ni)
                mma16816(acc[mi][ni], av[mi], bh[ni]);

        // ---- ks = 1 ------------------------------------------------------
#pragma unroll
        for (int mi = 0; mi < 4; ++mi)     // A-hi
            ldm_x4(av[mi][0], av[mi][1], av[mi][2], av[mi][3],
                   aB + ((mi * 576 + 8) << 2));
#pragma unroll
        for (int np = 0; np < 2; ++np) {
            ldm_x4(bh[2 * np][0], bh[2 * np][1], bh[2 * np + 1][0], bh[2 * np + 1][1],
                   bB + ((np * 576 + 8) << 2));
            ldm_x4(bl[2 * np][0], bl[2 * np][1], bl[2 * np + 1][0], bl[2 * np + 1][1],
                   bB + ((np * 576 + 24) << 2));
        }
#pragma unroll
        for (int mi = 0; mi < 4; ++mi)     // hh
#pragma unroll
            for (int ni = 0; ni < 4; ++ni)
                mma16816(acc[mi][ni], av[mi], bh[ni]);
#pragma unroll
        for (int mi = 0; mi < 4; ++mi)     // hl
#pragma unroll
            for (int ni = 0; ni < 4; ++ni)
                mma16816(acc[mi][ni], av[mi], bl[ni]);
#pragma unroll
        for (int mi = 0; mi < 4; ++mi)     // A-lo
            ldm_x4(av[mi][0], av[mi][1], av[mi][2], av[mi][3],
                   aB + ((mi * 576 + 24) << 2));
#pragma unroll
        for (int mi = 0; mi < 4; ++mi)     // lh
#pragma unroll
            for (int ni = 0; ni < 4; ++ni)
                mma16816(acc[mi][ni], av[mi], bh[ni]);
    }
}

__device__ __forceinline__ float silu(float v) { return v / (1.0f + __expf(-v)); }

// Per-thread element coordinates inside the 128x128 tile:
//   r = wm*64 + mi*16 + g + (e>=2 ? 8 : 0)
//   c = wn*32 + ni*8 + tg*2 + (e&1)

// ---------------------------------------------------------------------------
// K0: elementwise fp32 -> bf16 hi/lo split (for x, proj_w, out_w)
// ---------------------------------------------------------------------------
__global__ void k_split(const float* __restrict__ src,
                        __nv_bfloat16* __restrict__ hi,
                        __nv_bfloat16* __restrict__ lo, int n)
{
    int i = (blockIdx.x * blockDim.x + threadIdx.x) * 4;
    if (i < n) {
        float4 f = *(const float4*)(src + i);
        __nv_bfloat16 h[4], l[4];
        split2(f.x, h[0], l[0]); split2(f.y, h[1], l[1]);
        split2(f.z, h[2], l[2]); split2(f.w, h[3], l[3]);
        *(uint2*)(hi + i) = *(const uint2*)h;
        *(uint2*)(lo + i) = *(const uint2*)l;
    }
}

// ---------------------------------------------------------------------------
// K1: proj = silu(x @ Wp^T + bp); split into u / vT(hi,lo) / q,k
// ---------------------------------------------------------------------------
__global__ void __launch_bounds__(GEMM_THREADS, 2)
k_proj_t(const float* __restrict__ pb, const float* __restrict__ gamma,
         const float* __restrict__ beta)
{
    const int bx = blockIdx.x, by = blockIdx.y;
    float acc[4][4][4] = {};
    mma_gemm(d_xh + (size_t)by * 128 * EDIM, d_xl + (size_t)by * 128 * EDIM, EDIM,
             d_pwh + (size_t)bx * 128 * EDIM, d_pwl + (size_t)bx * 128 * EDIM, EDIM,
             EDIM / 32, acc);

    const int lane = threadIdx.x & 31, wid = threadIdx.x >> 5;
    const int g = lane >> 2, tg = lane & 3;
    const int wm = wid & 1, wn = wid >> 1;
#pragma unroll
    for (int mi = 0; mi < 4; ++mi) {
#pragma unroll
        for (int ni = 0; ni < 4; ++ni) {
#pragma unroll
            for (int e = 0; e < 4; ++e) {
                int r = by * 128 + wm * 64 + mi * 16 + g + ((e >> 1) ? 8 : 0);
                int cg = bx * 128 + wn * 32 + ni * 8 + tg * 2 + (e & 1);
                float v = silu(acc[mi][ni][e] + pb[cg]);
                int s = r >> 2, b = r & 3;
                if (bx < 16) {
                    d_u[(size_t)r * HDIM + cg] = v;
                } else if (bx < 32) {
                    int h = cg - HDIM;
                    size_t vi = ((size_t)b * HDIM + h) * S_LEN + s;
                    __nv_bfloat16 vh, vl;
                    split2(v, vh, vl);
                    d_vTh[vi] = vh;
                    d_vTl[vi] = vl;
                } else {
                    int zi = cg - 2 * HDIM;
                    size_t qi = ((size_t)b * S_LEN + s) * ZDIM + zi;
                    d_q[qi]  = v * gamma[zi]        + beta[zi];
                    d_kk[qi] = v * gamma[ZDIM + zi] + beta[ZDIM + zi];
                }
            }
        }
    }
}

// ---------------------------------------------------------------------------
// K2: scores = relu(q k^T / S + bias)^2, causal -> attn hi/lo (fp32 FFMA)
// ---------------------------------------------------------------------------
#define BK 16
__global__ void __launch_bounds__(SCORE_THREADS, 2)
k_score(const float* __restrict__ rpb)
{
    const int by = blockIdx.y, bx = blockIdx.x, b = blockIdx.z;
    if (bx > by) return;
    __shared__ float As[BK][129];
    __shared__ float Bs[BK][129];
    float acc[8][8] = {};
    const float* Ag0 = d_q  + ((size_t)b * S_LEN + by * 128) * ZDIM;
    const float* Bg0 = d_kk + ((size_t)b * S_LEN + bx * 128) * ZDIM;
    const int tid = threadIdx.x;
    const int lr = tid >> 2, lc = (tid & 3) << 2;
    const float* Ag = Ag0 + lr * ZDIM + lc;
    const float* Bg = Bg0 + lr * ZDIM + lc;
    const int ty = tid >> 4, tx = tid & 15;
    for (int kk = 0; kk < ZDIM / BK; ++kk) {
        float4 a0 = *(const float4*)(Ag);
        float4 a1 = *(const float4*)(Ag + 64 * ZDIM);
        float4 b0 = *(const float4*)(Bg);
        float4 b1 = *(const float4*)(Bg + 64 * ZDIM);
        __syncthreads();
        As[lc + 0][lr] = a0.x; As[lc + 1][lr] = a0.y; As[lc + 2][lr] = a0.z; As[lc + 3][lr] = a0.w;
        As[lc + 0][lr + 64] = a1.x; As[lc + 1][lr + 64] = a1.y; As[lc + 2][lr + 64] = a1.z; As[lc + 3][lr + 64] = a1.w;
        Bs[lc + 0][lr] = b0.x; Bs[lc + 1][lr] = b0.y; Bs[lc + 2][lr] = b0.z; Bs[lc + 3][lr] = b0.w;
        Bs[lc + 0][lr + 64] = b1.x; Bs[lc + 1][lr + 64] = b1.y; Bs[lc + 2][lr + 64] = b1.z; Bs[lc + 3][lr + 64] = b1.w;
        __syncthreads();
#pragma unroll
        for (int k = 0; k < BK; ++k) {
            float ar[8], br[8];
#pragma unroll
            for (int i = 0; i < 8; ++i) ar[i] = As[k][i * 16 + ty];
#pragma unroll
            for (int j = 0; j < 8; ++j) br[j] = Bs[k][j * 16 + tx];
#pragma unroll
            for (int i = 0; i < 8; ++i)
#pragma unroll
                for (int j = 0; j < 8; ++j) acc[i][j] += ar[i] * br[j];
        }
        Ag += BK; Bg += BK;
    }
#pragma unroll
    for (int i = 0; i < 8; ++i) {
#pragma unroll
        for (int j = 0; j < 8; ++j) {
            int r = by * 128 + i * 16 + ty;
            int c = bx * 128 + j * 16 + tx;
            float v = acc[i][j] * (1.0f / (float)S_LEN) + rpb[(S_LEN - 1) + c - r];
            float a = (c > r) ? 0.0f : fmaxf(v, 0.0f);
            float a2 = a * a;
            size_t idx = ((size_t)b * S_LEN + r) * S_LEN + c;
            __nv_bfloat16 h, l;
            split2(a2, h, l);
            d_ah[idx] = h;
            d_al[idx] = l;
        }
    }
}

// ---------------------------------------------------------------------------
// K3: g = (attn @ v) * u  (K truncated at diagonal) -> g hi/lo
// ---------------------------------------------------------------------------
__global__ void __launch_bounds__(GEMM_THREADS, 2)
k_av_t()
{
    const int bx = blockIdx.x, by = blockIdx.y, b = blockIdx.z;
    float acc[4][4][4] = {};
    mma_gemm(d_ah + ((size_t)b * S_LEN + by * 128) * S_LEN,
             d_al + ((size_t)b * S_LEN + by * 128) * S_LEN, S_LEN,
             d_vTh + ((size_t)b * HDIM + bx * 128) * S_LEN,
             d_vTl + ((size_t)b * HDIM + bx * 128) * S_LEN, S_LEN,
             (by + 1) * 4, acc);

    const int lane = threadIdx.x & 31, wid = threadIdx.x >> 5;
    const int g = lane >> 2, tg = lane & 3;
    const int wm = wid & 1, wn = wid >> 1;
#pragma unroll
    for (int mi = 0; mi < 4; ++mi) {
#pragma unroll
        for (int ni = 0; ni < 4; ++ni) {
#pragma unroll
            for (int e = 0; e < 4; ++e) {
                int q = by * 128 + wm * 64 + mi * 16 + g + ((e >> 1) ? 8 : 0);
                int h = bx * 128 + wn * 32 + ni * 8 + tg * 2 + (e & 1);
                size_t idx = ((size_t)q * BSZ + b) * HDIM + h;
                float gv = acc[mi][ni][e] * d_u[idx];
                __nv_bfloat16 gh, gl;
                split2(gv, gh, gl);
                d_gh[idx] = gh;
                d_gl[idx] = gl;
            }
        }
    }
}

// ---------------------------------------------------------------------------
// K4: out = g @ Wo^T + bo
// ---------------------------------------------------------------------------
__global__ void __launch_bounds__(GEMM_THREADS, 2)
k_out_t(const float* __restrict__ ob, float* __restrict__ out)
{
    const int bx = blockIdx.x, by = blockIdx.y;
    float acc[4][4][4] = {};
    mma_gemm(d_gh + (size_t)by * 128 * HDIM, d_gl + (size_t)by * 128 * HDIM, HDIM,
             d_owh + (size_t)bx * 128 * HDIM, d_owl + (size_t)bx * 128 * HDIM, HDIM,
             HDIM / 32, acc);

    const int lane = threadIdx.x & 31, wid = threadIdx.x >> 5;
    const int g = lane >> 2, tg = lane & 3;
    const int wm = wid & 1, wn = wid >> 1;
#pragma unroll
    for (int mi = 0; mi < 4; ++mi) {
#pragma unroll
        for (int ni = 0; ni < 4; ++ni) {
#pragma unroll
            for (int e = 0; e < 4; ++e) {
                int r = by * 128 + wm * 64 + mi * 16 + g + ((e >> 1) ? 8 : 0);
                int c = bx * 128 + wn * 32 + ni * 8 + tg * 2 + (e & 1);
                out[(size_t)r * EDIM + c] = acc[mi][ni][e] + ob[c];
            }
        }
    }
}

// ---------------------------------------------------------------------------
extern "C" void kernel_launch(void* const* d_in, const int* in_sizes, int n_in,
                              void* d_out, int out_size)
{
    const float* x      = (const float*)d_in[0];
    const float* proj_w = (const float*)d_in[2];
    const float* proj_b = (const float*)d_in[3];
    const float* out_w  = (const float*)d_in[4];
    const float* out_b  = (const float*)d_in[5];
    const float* gamma  = (const float*)d_in[6];
    const float* beta   = (const float*)d_in[7];
    const float* rpb    = (const float*)d_in[8];
    float* out = (float*)d_out;

    cudaFuncSetAttribute(k_proj_t, cudaFuncAttributeMaxDynamicSharedMemorySize, SMEM_DYN_BYTES);
    cudaFuncSetAttribute(k_av_t,   cudaFuncAttributeMaxDynamicSharedMemorySize, SMEM_DYN_BYTES);
    cudaFuncSetAttribute(k_out_t,  cudaFuncAttributeMaxDynamicSharedMemorySize, SMEM_DYN_BYTES);

    __nv_bfloat16 *xh, *xl, *pwh, *pwl, *owh, *owl;
    cudaGetSymbolAddress((void**)&xh,  d_xh);
    cudaGetSymbolAddress((void**)&xl,  d_xl);
    cudaGetSymbolAddress((void**)&pwh, d_pwh);
    cudaGetSymbolAddress((void**)&pwl, d_pwl);
    cudaGetSymbolAddress((void**)&owh, d_owh);
    cudaGetSymbolAddress((void**)&owl, d_owl);

    const int nx = S_LEN * BSZ * EDIM;
    const int npw = (2 * HDIM + ZDIM) * EDIM;
    const int now = EDIM * HDIM;
    k_split<<<nx  / 1024, 256>>>(x,      xh,  xl,  nx);
    k_split<<<npw / 1024, 256>>>(proj_w, pwh, pwl, npw);
    k_split<<<now / 1024, 256>>>(out_w,  owh, owl, now);

    k_proj_t<<<dim3(33, 64), dim3(GEMM_THREADS), SMEM_DYN_BYTES>>>(proj_b, gamma, beta);
    k_score <<<dim3(16, 16, 4), dim3(SCORE_THREADS)>>>(rpb);
    k_av_t  <<<dim3(16, 16, 4), dim3(GEMM_THREADS), SMEM_DYN_BYTES>>>();
    k_out_t <<<dim3(8, 64), dim3(GEMM_THREADS), SMEM_DYN_BYTES>>>(out_b, out);
}